// round 8
// baseline (speedup 1.0000x reference)
#include <cuda_runtime.h>
#include <math.h>

// Problem constants (fixed by reference)
#define TT   1024
#define BB   64
#define HH   512
#define H2   1024
#define SZ   (BB * HH)        // 32768 elems per state
#define NCTA 128
#define NTHR 256

// Scratch (device globals: allocation-free). Slots: 0:s0 1:s1 2:s2 3:s3 4:s5
__device__ __align__(16) float g_state[5 * SZ];
__device__ __align__(16) float g_h[SZ];
__device__ unsigned long long g_bar = 0ULL;   // monotonic barrier counter (replay-safe)

__device__ __forceinline__ void grid_bar() {
    __syncthreads();
    if (threadIdx.x == 0) {
        __threadfence();
        unsigned long long my = atomicAdd(&g_bar, 1ULL);
        unsigned long long target = (my / (unsigned long long)NCTA + 1ULL) * (unsigned long long)NCTA;
        while (*((volatile unsigned long long*)&g_bar) < target) {
            __nanosleep(64);
        }
        __threadfence();
    }
    __syncthreads();
}

__device__ __forceinline__ float sigm(float x) { return 1.0f / (1.0f + expf(-x)); }

// Dot of one state row (512 floats, as 128 float4) against NN weight-column
// pairs held in SMEM. Weight layout: per node, float2[k][4jj] with the jj
// offset pre-applied to the pointer, so element k lives at wp[n][k*4].
template <int NN>
__device__ __forceinline__ void dotN(const float* __restrict__ srow,
                                     const float2* const* wp,
                                     float* aC, float* aH) {
    float c[NN], h[NN];
#pragma unroll
    for (int n = 0; n < NN; n++) { c[n] = 0.0f; h[n] = 0.0f; }
    const float4* s4 = (const float4*)srow;
#pragma unroll 4
    for (int kk = 0; kk < 128; kk++) {
        float4 sv = s4[kk];
        const int o = kk * 16;
#pragma unroll
        for (int n = 0; n < NN; n++) {
            float2 w0v = wp[n][o];
            float2 w1v = wp[n][o + 4];
            float2 w2v = wp[n][o + 8];
            float2 w3v = wp[n][o + 12];
            c[n] = fmaf(sv.x, w0v.x, c[n]); h[n] = fmaf(sv.x, w0v.y, h[n]);
            c[n] = fmaf(sv.y, w1v.x, c[n]); h[n] = fmaf(sv.y, w1v.y, h[n]);
            c[n] = fmaf(sv.z, w2v.x, c[n]); h[n] = fmaf(sv.z, w2v.y, h[n]);
            c[n] = fmaf(sv.w, w3v.x, c[n]); h[n] = fmaf(sv.w, w3v.y, h[n]);
        }
    }
#pragma unroll
    for (int n = 0; n < NN; n++) { aC[n] = c[n]; aH[n] = h[n]; }
}

// SMEM: W0 slice 1024k x 4jj float2 (32KB) + 8 nodes x 512k x 4jj float2 (128KB) = 160KB
#define SMEM_BYTES (163840)

__global__ void __launch_bounds__(NTHR, 1)
darts_kernel(const float* __restrict__ x,
             const float* __restrict__ W0,
             const float* __restrict__ Ws,
             float* __restrict__ out) {
    extern __shared__ float sm[];
    float2* w0s = (float2*)sm;            // [1024][4]
    float2* wns = (float2*)sm + 4096;     // 8 x [512][4]

    const int cid = blockIdx.x;
    const int tid = threadIdx.x;
    const int Jb  = cid * 4;

    // ---- Load weight column slices into SMEM (once; reused for 1024 steps) ----
    for (int p = tid; p < 4096; p += NTHR) {
        int k = p >> 2, jj = p & 3, J = Jb + jj;
        w0s[p] = make_float2(W0[k * H2 + J], W0[k * H2 + J + HH]);
    }
    for (int i = 0; i < 8; i++) {
        const float* Wi = Ws + (size_t)i * HH * H2;
        float2* d = wns + i * 2048;
        for (int p = tid; p < 2048; p += NTHR) {
            int k = p >> 2, jj = p & 3, J = Jb + jj;
            d[p] = make_float2(Wi[k * H2 + J], Wi[k * H2 + J + HH]);
        }
    }

    const int b  = tid >> 2;       // 0..63
    const int jj = tid & 3;        // 0..3
    const int J  = Jb + jj;        // owned state column
    const int eidx = b * HH + J;   // (b, J) element index

    g_h[eidx] = 0.0f;              // h0 = zeros
    float hprev = 0.0f;

    const float2* wn[8];
#pragma unroll
    for (int i = 0; i < 8; i++) wn[i] = wns + i * 2048 + jj;
    const float2* w0a = w0s + jj;             // k in [0,512)   (x part)
    const float2* w0b = w0s + 512 * 4 + jj;   // k in [512,1024) (h part)

    grid_bar();  // g_h init visible everywhere

    for (int t = 0; t < TT; t++) {
        // ================= LVL0: init state s0 (K=1024 over [x, h_prev]) =================
        float aC, aH;
        {
            float cx, hx, ch, hh2;
            const float2* pa[1] = { w0a };
            dotN<1>(x + (size_t)t * SZ + (size_t)b * HH, pa, &cx, &hx);
            const float2* pb[1] = { w0b };
            dotN<1>(g_h + b * HH, pb, &ch, &hh2);
            aC = cx + ch; aH = hx + hh2;
        }
        float s0 = hprev + sigm(aC) * (tanhf(aH) - hprev);
        g_state[0 * SZ + eidx] = s0;
        grid_bar();

        // ================= LVL1: node0 (pred s0, act sigmoid) -> s1 =================
        float a1C, a1H;
        {
            const float2* p[1] = { wn[0] };
            dotN<1>(g_state + 0 * SZ + b * HH, p, &a1C, &a1H);
        }
        float s1 = s0 + sigm(a1C) * (sigm(a1H) - s0);
        g_state[1 * SZ + eidx] = s1;
        grid_bar();

        // ========== LVL2: nodes 1,2,3 (pred s1; relu, relu, identity) -> s2,s3,s4 ==========
        float aCn[3], aHn[3];
        {
            const float2* p[3] = { wn[1], wn[2], wn[3] };
            dotN<3>(g_state + 1 * SZ + b * HH, p, aCn, aHn);
        }
        float s2 = s1 + sigm(aCn[0]) * (fmaxf(aHn[0], 0.0f) - s1);
        float s3 = s1 + sigm(aCn[1]) * (fmaxf(aHn[1], 0.0f) - s1);
        float s4 = s1 + sigm(aCn[2]) * (aHn[2] - s1);
        g_state[2 * SZ + eidx] = s2;
        g_state[3 * SZ + eidx] = s3;
        grid_bar();

        // ========== LVL3: node4 (pred s2, tanh) -> s5 ; node6 (pred s3, tanh) -> s7 ==========
        float a4C, a4H, a6C, a6H;
        {
            const float2* p4[1] = { wn[4] };
            dotN<1>(g_state + 2 * SZ + b * HH, p4, &a4C, &a4H);
            const float2* p6[1] = { wn[6] };
            dotN<1>(g_state + 3 * SZ + b * HH, p6, &a6C, &a6H);
        }
        float s5 = s2 + sigm(a4C) * (tanhf(a4H) - s2);
        float s7 = s3 + sigm(a6C) * (tanhf(a6H) - s3);
        g_state[4 * SZ + eidx] = s5;
        grid_bar();

        // ========== LVL4: node5 (pred s5, sigmoid) -> s6 ; node7 (pred s5, relu) -> s8 ==========
        float aC2[2], aH2[2];
        {
            const float2* p[2] = { wn[5], wn[7] };
            dotN<2>(g_state + 4 * SZ + b * HH, p, aC2, aH2);
        }
        float s6 = s5 + sigm(aC2[0]) * (sigm(aH2[0]) - s5);
        float s8 = s5 + sigm(aC2[1]) * (fmaxf(aH2[1], 0.0f) - s5);

        // Mean over concat states 1..8 — all local to this thread.
        float hn = (s1 + s2 + s3 + s4 + s5 + s6 + s7 + s8) * 0.125f;
        out[(size_t)t * SZ + eidx] = hn;
        g_h[eidx] = hn;
        hprev = hn;
        if (t == TT - 1) out[(size_t)TT * SZ + eidx] = hn;  // hiddens[-1][None] tail
        grid_bar();  // h_new visible before next step's LVL0
    }
}

extern "C" void kernel_launch(void* const* d_in, const int* in_sizes, int n_in,
                              void* d_out, int out_size) {
    const float* x  = (const float*)d_in[0];   // inputs (T, B, H) f32
    const float* W0 = (const float*)d_in[1];   // (2H, 2H) f32
    const float* Ws = (const float*)d_in[2];   // (8, H, 2H) f32
    float* out = (float*)d_out;                // (T*B*H + B*H) f32

    cudaFuncSetAttribute(darts_kernel,
                         cudaFuncAttributeMaxDynamicSharedMemorySize, SMEM_BYTES);
    darts_kernel<<<NCTA, NTHR, SMEM_BYTES>>>(x, W0, Ws, out);
}

// round 9
// speedup vs baseline: 1.4397x; 1.4397x over previous
#include <cuda_runtime.h>
#include <math.h>

// Problem constants
#define TT   1024
#define BB   64
#define HH   512
#define H2   1024
#define SZ   (BB * HH)         // 32768 elems per state
#define NCTA 128
#define NTHR 512

#define W0_PAD 1028            // 1024 + 4 pad floats (bank-conflict-free LDS.128)
#define WN_PAD 516             // 512 + 4 pad floats
#define SM_W0  (8 * W0_PAD)                 // 8224 floats
#define SM_WN  (8 * 8 * WN_PAD)             // 33024 floats
#define SM_RED (SM_W0 + SM_WN)              // 41248 floats (offset of red[])
#define SMEM_FLOATS (SM_RED + 3 * 512 * 2)  // + red[3][512] float2
#define SMEM_BYTES  (SMEM_FLOATS * 4)       // 177280 B

// Device-global scratch. State slots: 0:s0 1:s1 2:s2 3:s3 4:s5
__device__ __align__(16) float g_state[5 * SZ];
__device__ __align__(16) float g_h[SZ];
__device__ unsigned long long g_bar = 0ULL;   // monotonic, graph-replay-safe

__device__ __forceinline__ void grid_bar() {
    __syncthreads();
    if (threadIdx.x == 0) {
        __threadfence();   // flush this SM's pending state + (CCTL.IVALL) invalidate L1D
        unsigned long long my = atomicAdd(&g_bar, 1ULL);
        unsigned long long target = (my / (unsigned long long)NCTA + 1ULL) * (unsigned long long)NCTA;
        while (*((volatile unsigned long long*)&g_bar) < target) __nanosleep(64);
        __threadfence();
    }
    __syncthreads();
}

__device__ __forceinline__ float sigm(float x) { return 1.0f / (1.0f + expf(-x)); }

// Dot of TWO state rows (b0,b1) against NN weight columns in SMEM.
// Each weight column is contiguous over k (float4 per 4 k). Returns per node
// float2{acc_b0, acc_b1}. 4 partial sums per output break the FMA chain.
template <int NN>
__device__ __forceinline__ void dot2(const float4* __restrict__ r0,
                                     const float4* __restrict__ r1,
                                     const float4* const* wp, int n4,
                                     float2* out) {
    float4 a[NN], c[NN];
#pragma unroll
    for (int n = 0; n < NN; n++) {
        a[n] = make_float4(0.f, 0.f, 0.f, 0.f);
        c[n] = make_float4(0.f, 0.f, 0.f, 0.f);
    }
#pragma unroll 4
    for (int i = 0; i < n4; i++) {
        float4 x0 = r0[i];
        float4 x1 = r1[i];
#pragma unroll
        for (int n = 0; n < NN; n++) {
            float4 w = wp[n][i];
            a[n].x = fmaf(x0.x, w.x, a[n].x);
            a[n].y = fmaf(x0.y, w.y, a[n].y);
            a[n].z = fmaf(x0.z, w.z, a[n].z);
            a[n].w = fmaf(x0.w, w.w, a[n].w);
            c[n].x = fmaf(x1.x, w.x, c[n].x);
            c[n].y = fmaf(x1.y, w.y, c[n].y);
            c[n].z = fmaf(x1.z, w.z, c[n].z);
            c[n].w = fmaf(x1.w, w.w, c[n].w);
        }
    }
#pragma unroll
    for (int n = 0; n < NN; n++)
        out[n] = make_float2((a[n].x + a[n].y) + (a[n].z + a[n].w),
                             (c[n].x + c[n].y) + (c[n].z + c[n].w));
}

// Combine k-split + c/h partials from red[] for updater thread `tid` (even, <256).
#define COMBINE(slot, cc0, cc1, hh0, hh1)                                  \
    {                                                                      \
        float2 cA = red[(slot) * 512 + tid];                               \
        float2 cB = red[(slot) * 512 + tid + 256];                         \
        float2 hA = red[(slot) * 512 + tid + 1];                           \
        float2 hB = red[(slot) * 512 + tid + 257];                         \
        cc0 = cA.x + cB.x; cc1 = cA.y + cB.y;                              \
        hh0 = hA.x + hB.x; hh1 = hA.y + hB.y;                              \
    }

__global__ void __launch_bounds__(NTHR, 1)
darts_kernel(const float* __restrict__ x,
             const float* __restrict__ W0,
             const float* __restrict__ Ws,
             float* __restrict__ out) {
    extern __shared__ float sm[];
    float*  w0s = sm;               // [8 oc][1028 k]
    float*  wns = sm + SM_W0;       // 8 nodes x [8 oc][516 k]
    float2* red = (float2*)(sm + SM_RED);   // [3][512] partials

    const int tid = threadIdx.x;
    const int Jb  = blockIdx.x * 4;

    // ---- Load weight column slices (once; reused 1024 steps) ----
    // oc = jj*2 + part: part 0 = c-column (J), part 1 = h-column (J+512)
    for (int p = tid; p < 2048; p += NTHR) {
        int k = p >> 1, part = p & 1;
        float4 v = *(const float4*)(W0 + (size_t)k * H2 + Jb + part * HH);
        w0s[(0 + part) * W0_PAD + k] = v.x;
        w0s[(2 + part) * W0_PAD + k] = v.y;
        w0s[(4 + part) * W0_PAD + k] = v.z;
        w0s[(6 + part) * W0_PAD + k] = v.w;
    }
    for (int p = tid; p < 8192; p += NTHR) {
        int i = p >> 10;
        int r = p & 1023;
        int k = r >> 1, part = r & 1;
        float4 v = *(const float4*)(Ws + (size_t)i * HH * H2 + (size_t)k * H2 + Jb + part * HH);
        float* d = wns + i * 8 * WN_PAD;
        d[(0 + part) * WN_PAD + k] = v.x;
        d[(2 + part) * WN_PAD + k] = v.y;
        d[(4 + part) * WN_PAD + k] = v.z;
        d[(6 + part) * WN_PAD + k] = v.w;
    }

    // ---- Thread decomposition for dots ----
    const int oc = tid & 7;            // output column: jj*2 + half(c/h)
    const int bp = (tid >> 3) & 31;    // batch pair
    const int ks = tid >> 8;           // k-split half
    const int b0 = bp * 2, b1 = b0 + 1;

    const float4* w0p = (const float4*)(w0s + oc * W0_PAD) + ks * 128;
    const float4* wnp[8];
#pragma unroll
    for (int i = 0; i < 8; i++)
        wnp[i] = (const float4*)(wns + (i * 8 + oc) * WN_PAD) + ks * 64;

    // ---- Updater identity: even threads of ks=0 half own 2 (b,J) elements ----
    const bool upd = (tid < 256) && ((tid & 1) == 0);
    const int uJ = Jb + ((tid >> 1) & 3);
    const int e0 = b0 * HH + uJ;       // (bp decode identical for tid<256)
    const int e1 = e0 + HH;

    if (blockIdx.x == 0)
        for (int i = tid; i < SZ; i += NTHR) g_h[i] = 0.f;

    // per-updater state registers
    float s0a, s0b, s1a, s1b, s2a, s2b, s3a, s3b, s5a, s5b, suma, sumb;
    s0a = s0b = s1a = s1b = s2a = s2b = s3a = s3b = s5a = s5b = suma = sumb = 0.f;

    grid_bar();   // g_h zeros visible

    for (int t = 0; t < TT; t++) {
        // ===== LVL0: init state s0. K=1024 over [x | h_prev]; ks picks the source =====
        {
            const float4 *r0, *r1;
            if (ks == 0) {
                const float4* xb = (const float4*)(x + (size_t)t * SZ);
                r0 = xb + b0 * 128; r1 = xb + b1 * 128;
            } else {
                r0 = (const float4*)g_h + b0 * 128;
                r1 = (const float4*)g_h + b1 * 128;
            }
            float2 o; const float4* wp1[1] = { w0p };
            dot2<1>(r0, r1, wp1, 128, &o);
            red[tid] = o;
        }
        __syncthreads();
        if (upd) {
            float cc0, cc1, hh0, hh1;
            COMBINE(0, cc0, cc1, hh0, hh1);
            float hp0 = g_h[e0], hp1 = g_h[e1];
            s0a = hp0 + sigm(cc0) * (tanhf(hh0) - hp0);
            s0b = hp1 + sigm(cc1) * (tanhf(hh1) - hp1);
            g_state[0 * SZ + e0] = s0a;
            g_state[0 * SZ + e1] = s0b;
        }
        grid_bar();

        // ===== LVL1: node0 (pred s0, sigmoid) -> s1 =====
        {
            const float4* sb = (const float4*)(g_state + 0 * SZ);
            const float4* r0 = sb + b0 * 128 + ks * 64;
            const float4* r1 = sb + b1 * 128 + ks * 64;
            float2 o; const float4* wp1[1] = { wnp[0] };
            dot2<1>(r0, r1, wp1, 64, &o);
            red[tid] = o;
        }
        __syncthreads();
        if (upd) {
            float cc0, cc1, hh0, hh1;
            COMBINE(0, cc0, cc1, hh0, hh1);
            s1a = s0a + sigm(cc0) * (sigm(hh0) - s0a);
            s1b = s0b + sigm(cc1) * (sigm(hh1) - s0b);
            g_state[1 * SZ + e0] = s1a;
            g_state[1 * SZ + e1] = s1b;
            suma = s1a; sumb = s1b;
        }
        grid_bar();

        // ===== LVL2: nodes 1,2,3 (pred s1; relu, relu, identity) -> s2,s3,s4 =====
        {
            const float4* sb = (const float4*)(g_state + 1 * SZ);
            const float4* r0 = sb + b0 * 128 + ks * 64;
            const float4* r1 = sb + b1 * 128 + ks * 64;
            float2 o[3]; const float4* wp3[3] = { wnp[1], wnp[2], wnp[3] };
            dot2<3>(r0, r1, wp3, 64, o);
            red[tid]        = o[0];
            red[512 + tid]  = o[1];
            red[1024 + tid] = o[2];
        }
        __syncthreads();
        if (upd) {
            float cc0, cc1, hh0, hh1;
            COMBINE(0, cc0, cc1, hh0, hh1);
            s2a = s1a + sigm(cc0) * (fmaxf(hh0, 0.f) - s1a);
            s2b = s1b + sigm(cc1) * (fmaxf(hh1, 0.f) - s1b);
            COMBINE(1, cc0, cc1, hh0, hh1);
            s3a = s1a + sigm(cc0) * (fmaxf(hh0, 0.f) - s1a);
            s3b = s1b + sigm(cc1) * (fmaxf(hh1, 0.f) - s1b);
            COMBINE(2, cc0, cc1, hh0, hh1);
            float s4a = s1a + sigm(cc0) * (hh0 - s1a);
            float s4b = s1b + sigm(cc1) * (hh1 - s1b);
            g_state[2 * SZ + e0] = s2a; g_state[2 * SZ + e1] = s2b;
            g_state[3 * SZ + e0] = s3a; g_state[3 * SZ + e1] = s3b;
            suma += s2a + s3a + s4a;
            sumb += s2b + s3b + s4b;
        }
        grid_bar();

        // ===== LVL3: node4 (pred s2, tanh) -> s5 ; node6 (pred s3, tanh) -> s7 =====
        {
            const float4* sb2 = (const float4*)(g_state + 2 * SZ);
            const float4* sb3 = (const float4*)(g_state + 3 * SZ);
            float2 o;
            const float4* wp4[1] = { wnp[4] };
            dot2<1>(sb2 + b0 * 128 + ks * 64, sb2 + b1 * 128 + ks * 64, wp4, 64, &o);
            red[tid] = o;
            const float4* wp6[1] = { wnp[6] };
            dot2<1>(sb3 + b0 * 128 + ks * 64, sb3 + b1 * 128 + ks * 64, wp6, 64, &o);
            red[512 + tid] = o;
        }
        __syncthreads();
        if (upd) {
            float cc0, cc1, hh0, hh1;
            COMBINE(0, cc0, cc1, hh0, hh1);
            s5a = s2a + sigm(cc0) * (tanhf(hh0) - s2a);
            s5b = s2b + sigm(cc1) * (tanhf(hh1) - s2b);
            COMBINE(1, cc0, cc1, hh0, hh1);
            float s7a = s3a + sigm(cc0) * (tanhf(hh0) - s3a);
            float s7b = s3b + sigm(cc1) * (tanhf(hh1) - s3b);
            g_state[4 * SZ + e0] = s5a;
            g_state[4 * SZ + e1] = s5b;
            suma += s5a + s7a;
            sumb += s5b + s7b;
        }
        grid_bar();

        // ===== LVL4: node5 (pred s5, sigmoid) -> s6 ; node7 (pred s5, relu) -> s8 =====
        {
            const float4* sb = (const float4*)(g_state + 4 * SZ);
            const float4* r0 = sb + b0 * 128 + ks * 64;
            const float4* r1 = sb + b1 * 128 + ks * 64;
            float2 o[2]; const float4* wp2[2] = { wnp[5], wnp[7] };
            dot2<2>(r0, r1, wp2, 64, o);
            red[tid]       = o[0];
            red[512 + tid] = o[1];
        }
        __syncthreads();
        if (upd) {
            float cc0, cc1, hh0, hh1;
            COMBINE(0, cc0, cc1, hh0, hh1);
            float s6a = s5a + sigm(cc0) * (sigm(hh0) - s5a);
            float s6b = s5b + sigm(cc1) * (sigm(hh1) - s5b);
            COMBINE(1, cc0, cc1, hh0, hh1);
            float s8a = s5a + sigm(cc0) * (fmaxf(hh0, 0.f) - s5a);
            float s8b = s5b + sigm(cc1) * (fmaxf(hh1, 0.f) - s5b);
            suma += s6a + s8a;
            sumb += s6b + s8b;
            float hn0 = suma * 0.125f;
            float hn1 = sumb * 0.125f;
            out[(size_t)t * SZ + e0] = hn0;
            out[(size_t)t * SZ + e1] = hn1;
            g_h[e0] = hn0;
            g_h[e1] = hn1;
            if (t == TT - 1) {                      // hiddens[-1][None] tail
                out[(size_t)TT * SZ + e0] = hn0;
                out[(size_t)TT * SZ + e1] = hn1;
            }
        }
        grid_bar();   // h_new visible before next step's LVL0
    }
}

extern "C" void kernel_launch(void* const* d_in, const int* in_sizes, int n_in,
                              void* d_out, int out_size) {
    const float* x  = (const float*)d_in[0];   // inputs (T, B, H) f32
    const float* W0 = (const float*)d_in[1];   // (2H, 2H) f32
    const float* Ws = (const float*)d_in[2];   // (8, H, 2H) f32
    float* out = (float*)d_out;

    cudaFuncSetAttribute(darts_kernel,
                         cudaFuncAttributeMaxDynamicSharedMemorySize, SMEM_BYTES);
    darts_kernel<<<NCTA, NTHR, SMEM_BYTES>>>(x, W0, Ws, out);
}

// round 10
// speedup vs baseline: 1.4974x; 1.0401x over previous
#include <cuda_runtime.h>
#include <math.h>

// Problem constants
#define TT   1024
#define BB   64
#define HH   512
#define H2   1024
#define SZ   (BB * HH)          // 32768 floats per state
#define NCTA 128
#define NTHR 512

#define W0_PAD 1028             // 1024+4 pad: col stride 4112B -> jj banks {0,8,16,24}
#define WN_PAD 516              // 512+4 pad:  col stride 2064B -> same
#define SM_W0  (8 * W0_PAD)                  // 8224 floats
#define SM_WN  (8 * 8 * WN_PAD)              // 33024 floats
#define SM_RED (SM_W0 + SM_WN)               // 41248 floats
#define SMEM_FLOATS (SM_RED + 3 * 512 * 4)   // + red float4[3][512]
#define SMEM_BYTES  (SMEM_FLOATS * 4)        // 189568 B

typedef unsigned long long ull;

// Device-global scratch. State slots: 0:s0 1:s1 2:s2 3:s3 4:s5
__device__ __align__(16) float g_state[5 * SZ];
__device__ __align__(16) float g_h[SZ];
__device__ ull g_bar = 0ULL;    // monotonic counter: graph-replay-safe

__device__ __forceinline__ void grid_bar() {
    __syncthreads();
    if (threadIdx.x == 0) {
        __threadfence();        // publish this SM's state + invalidate L1D (CCTL.IVALL)
        ull my = atomicAdd(&g_bar, 1ULL);
        ull target = (my / (ull)NCTA + 1ULL) * (ull)NCTA;
        while (*((volatile ull*)&g_bar) < target) __nanosleep(64);
        __threadfence();
    }
    __syncthreads();
}

__device__ __forceinline__ float sigm(float x) { return 1.0f / (1.0f + expf(-x)); }

// Packed f32x2 FMA (sm_103a FFMA2): d.lo += a.lo*b.lo ; d.hi += a.hi*b.hi
__device__ __forceinline__ void fma2(ull& d, ull a, ull b) {
    asm("fma.rn.f32x2 %0, %1, %2, %0;" : "+l"(d) : "l"(a), "l"(b));
}
// Horizontal sum of two packed accumulators -> scalar
__device__ __forceinline__ float hsum2(ull a, ull b) {
    ull s; asm("add.rn.f32x2 %0, %1, %2;" : "=l"(s) : "l"(a), "l"(b));
    float lo, hi; asm("mov.b64 {%0,%1}, %2;" : "=f"(lo), "=f"(hi) : "l"(s));
    return lo + hi;
}

// Dot of 2 state rows against NN (c,h) weight-column pairs using packed f32x2.
// Each 16B vector = 2 f32x2 operands; 2 packed accums/output break the RAW chain.
// out[n] = {c_b0, c_b1, h_b0, h_b1}
template <int NN>
__device__ __forceinline__ void dot2p(const ulonglong2* __restrict__ r0,
                                      const ulonglong2* __restrict__ r1,
                                      const ulonglong2* const* wc,
                                      const ulonglong2* const* wh,
                                      int n4, float4* out) {
    ull a[NN][4][2];
#pragma unroll
    for (int n = 0; n < NN; n++)
#pragma unroll
        for (int q = 0; q < 4; q++) { a[n][q][0] = 0ULL; a[n][q][1] = 0ULL; }

#pragma unroll 8
    for (int i = 0; i < n4; i++) {
        ulonglong2 s0 = r0[i];
        ulonglong2 s1 = r1[i];
#pragma unroll
        for (int n = 0; n < NN; n++) {
            ulonglong2 c = wc[n][i];
            ulonglong2 h = wh[n][i];
            fma2(a[n][0][0], s0.x, c.x); fma2(a[n][0][1], s0.y, c.y);
            fma2(a[n][1][0], s1.x, c.x); fma2(a[n][1][1], s1.y, c.y);
            fma2(a[n][2][0], s0.x, h.x); fma2(a[n][2][1], s0.y, h.y);
            fma2(a[n][3][0], s1.x, h.x); fma2(a[n][3][1], s1.y, h.y);
        }
    }
#pragma unroll
    for (int n = 0; n < NN; n++)
        out[n] = make_float4(hsum2(a[n][0][0], a[n][0][1]),
                             hsum2(a[n][1][0], a[n][1][1]),
                             hsum2(a[n][2][0], a[n][2][1]),
                             hsum2(a[n][3][0], a[n][3][1]));
}

// Combine 4 k-split partials for updater thread tid (<128). v = {c0,c1,h0,h1}
#define COMB(slot, v)                                                       \
    float4 v; {                                                             \
        float4 p0 = red[(slot) * 512 + tid];                                \
        float4 p1 = red[(slot) * 512 + tid + 128];                          \
        float4 p2 = red[(slot) * 512 + tid + 256];                          \
        float4 p3 = red[(slot) * 512 + tid + 384];                          \
        v = make_float4(p0.x + p1.x + p2.x + p3.x,                          \
                        p0.y + p1.y + p2.y + p3.y,                          \
                        p0.z + p1.z + p2.z + p3.z,                          \
                        p0.w + p1.w + p2.w + p3.w);                         \
    }

__global__ void __launch_bounds__(NTHR, 1)
darts_kernel(const float* __restrict__ x,
             const float* __restrict__ W0,
             const float* __restrict__ Ws,
             float* __restrict__ out) {
    extern __shared__ float sm[];
    float*  w0s = sm;                       // [8 oc][1028]
    float*  wns = sm + SM_W0;               // [8 node][8 oc][516]
    float4* red = (float4*)(sm + SM_RED);   // [3][512]

    const int tid = threadIdx.x;
    const int Jb  = blockIdx.x * 4;

    // ---- Stage weight column slices into SMEM (once; reused 1024 steps) ----
    // oc = jj*2 + part: part0 = c-col (J), part1 = h-col (J+512)
    for (int p = tid; p < 8 * 1024; p += NTHR) {
        int k = p >> 3, oc = p & 7;
        int J = Jb + (oc >> 1) + (oc & 1) * HH;
        w0s[oc * W0_PAD + k] = W0[(size_t)k * H2 + J];
    }
    for (int p = tid; p < 8 * 8 * 512; p += NTHR) {
        int node = p >> 12, r = p & 4095;
        int k = r >> 3, oc = r & 7;
        int J = Jb + (oc >> 1) + (oc & 1) * HH;
        wns[(node * 8 + oc) * WN_PAD + k] =
            Ws[(size_t)node * HH * H2 + (size_t)k * H2 + J];
    }

    // ---- Thread decomposition: tid = jj + 4*bp + 128*ks ----
    const int jj = tid & 3;
    const int bp = (tid >> 2) & 31;
    const int ks = tid >> 7;
    const int b0 = bp * 2, b1 = b0 + 1;

    const ulonglong2* w0c = (const ulonglong2*)(w0s + (2 * jj) * W0_PAD) + ks * 64;
    const ulonglong2* w0h = (const ulonglong2*)(w0s + (2 * jj + 1) * W0_PAD) + ks * 64;
    const ulonglong2* wnc[8];
    const ulonglong2* wnh[8];
#pragma unroll
    for (int i = 0; i < 8; i++) {
        wnc[i] = (const ulonglong2*)(wns + (i * 8 + 2 * jj) * WN_PAD) + ks * 32;
        wnh[i] = (const ulonglong2*)(wns + (i * 8 + 2 * jj + 1) * WN_PAD) + ks * 32;
    }
    const int ko = ks * 32;   // state k-offset (ulonglong2 units) for K=512 levels

    // ---- Updater identity: tid<128 owns elements (b0,J) and (b1,J) ----
    const bool upd = (tid < 128);
    const int J  = Jb + jj;
    const int e0 = b0 * HH + J;
    const int e1 = e0 + HH;

    if (blockIdx.x == 0)
        for (int i = tid; i < SZ; i += NTHR) g_h[i] = 0.f;

    // per-updater live state registers
    float hp0 = 0.f, hp1 = 0.f;
    float s0a = 0.f, s0b = 0.f, s1a = 0.f, s1b = 0.f;
    float s2a = 0.f, s2b = 0.f, s3a = 0.f, s3b = 0.f;
    float s5a = 0.f, s5b = 0.f, suma = 0.f, sumb = 0.f;

    grid_bar();   // weights staged + g_h zeros visible

    for (int t = 0; t < TT; t++) {
        // ===== LVL0: s0, K=1024 over [x | h_prev]; ks 0,1 -> x, ks 2,3 -> g_h =====
        {
            const ulonglong2 *r0, *r1;
            if (ks < 2) {
                const float* xb = x + (size_t)t * SZ;
                r0 = (const ulonglong2*)(xb + b0 * HH) + ks * 64;
                r1 = (const ulonglong2*)(xb + b1 * HH) + ks * 64;
            } else {
                r0 = (const ulonglong2*)(g_h + b0 * HH) + (ks - 2) * 64;
                r1 = (const ulonglong2*)(g_h + b1 * HH) + (ks - 2) * 64;
            }
            float4 o;
            const ulonglong2* c1a[1] = { w0c };
            const ulonglong2* h1a[1] = { w0h };
            dot2p<1>(r0, r1, c1a, h1a, 64, &o);
            red[tid] = o;
        }
        __syncthreads();
        if (upd) {
            COMB(0, v);
            s0a = hp0 + sigm(v.x) * (tanhf(v.z) - hp0);
            s0b = hp1 + sigm(v.y) * (tanhf(v.w) - hp1);
            g_state[0 * SZ + e0] = s0a;
            g_state[0 * SZ + e1] = s0b;
        }
        grid_bar();

        // ===== LVL1: node0 (pred s0, sigmoid) -> s1 =====
        {
            const ulonglong2* sb0 = (const ulonglong2*)(g_state + 0 * SZ + b0 * HH) + ko;
            const ulonglong2* sb1 = (const ulonglong2*)(g_state + 0 * SZ + b1 * HH) + ko;
            float4 o;
            const ulonglong2* c1a[1] = { wnc[0] };
            const ulonglong2* h1a[1] = { wnh[0] };
            dot2p<1>(sb0, sb1, c1a, h1a, 32, &o);
            red[tid] = o;
        }
        __syncthreads();
        if (upd) {
            COMB(0, v);
            s1a = s0a + sigm(v.x) * (sigm(v.z) - s0a);
            s1b = s0b + sigm(v.y) * (sigm(v.w) - s0b);
            g_state[1 * SZ + e0] = s1a;
            g_state[1 * SZ + e1] = s1b;
            suma = s1a; sumb = s1b;
        }
        grid_bar();

        // ===== LVL2: nodes 1,2,3 (pred s1; relu, relu, identity) =====
        {
            const ulonglong2* sb0 = (const ulonglong2*)(g_state + 1 * SZ + b0 * HH) + ko;
            const ulonglong2* sb1 = (const ulonglong2*)(g_state + 1 * SZ + b1 * HH) + ko;
            float4 o[3];
            const ulonglong2* c3a[3] = { wnc[1], wnc[2], wnc[3] };
            const ulonglong2* h3a[3] = { wnh[1], wnh[2], wnh[3] };
            dot2p<3>(sb0, sb1, c3a, h3a, 32, o);
            red[tid]        = o[0];
            red[512 + tid]  = o[1];
            red[1024 + tid] = o[2];
        }
        __syncthreads();
        if (upd) {
            COMB(0, v2);
            s2a = s1a + sigm(v2.x) * (fmaxf(v2.z, 0.f) - s1a);
            s2b = s1b + sigm(v2.y) * (fmaxf(v2.w, 0.f) - s1b);
            COMB(1, v3);
            s3a = s1a + sigm(v3.x) * (fmaxf(v3.z, 0.f) - s1a);
            s3b = s1b + sigm(v3.y) * (fmaxf(v3.w, 0.f) - s1b);
            COMB(2, v4);
            float s4a = s1a + sigm(v4.x) * (v4.z - s1a);
            float s4b = s1b + sigm(v4.y) * (v4.w - s1b);
            g_state[2 * SZ + e0] = s2a; g_state[2 * SZ + e1] = s2b;
            g_state[3 * SZ + e0] = s3a; g_state[3 * SZ + e1] = s3b;
            suma += s2a + s3a + s4a;
            sumb += s2b + s3b + s4b;
        }
        grid_bar();

        // ===== LVL3: node4 (pred s2, tanh) -> s5 ; node6 (pred s3, tanh) -> s7 =====
        {
            const ulonglong2* sa0 = (const ulonglong2*)(g_state + 2 * SZ + b0 * HH) + ko;
            const ulonglong2* sa1 = (const ulonglong2*)(g_state + 2 * SZ + b1 * HH) + ko;
            float4 o;
            const ulonglong2* c4a[1] = { wnc[4] };
            const ulonglong2* h4a[1] = { wnh[4] };
            dot2p<1>(sa0, sa1, c4a, h4a, 32, &o);
            red[tid] = o;
            const ulonglong2* sc0 = (const ulonglong2*)(g_state + 3 * SZ + b0 * HH) + ko;
            const ulonglong2* sc1 = (const ulonglong2*)(g_state + 3 * SZ + b1 * HH) + ko;
            const ulonglong2* c6a[1] = { wnc[6] };
            const ulonglong2* h6a[1] = { wnh[6] };
            dot2p<1>(sc0, sc1, c6a, h6a, 32, &o);
            red[512 + tid] = o;
        }
        __syncthreads();
        if (upd) {
            COMB(0, v5);
            s5a = s2a + sigm(v5.x) * (tanhf(v5.z) - s2a);
            s5b = s2b + sigm(v5.y) * (tanhf(v5.w) - s2b);
            COMB(1, v7);
            float s7a = s3a + sigm(v7.x) * (tanhf(v7.z) - s3a);
            float s7b = s3b + sigm(v7.y) * (tanhf(v7.w) - s3b);
            g_state[4 * SZ + e0] = s5a;
            g_state[4 * SZ + e1] = s5b;
            suma += s5a + s7a;
            sumb += s5b + s7b;
        }
        grid_bar();

        // ===== LVL4: node5 (pred s5, sigmoid) ; node7 (pred s5, relu) =====
        {
            const ulonglong2* sb0 = (const ulonglong2*)(g_state + 4 * SZ + b0 * HH) + ko;
            const ulonglong2* sb1 = (const ulonglong2*)(g_state + 4 * SZ + b1 * HH) + ko;
            float4 o[2];
            const ulonglong2* c2a[2] = { wnc[5], wnc[7] };
            const ulonglong2* h2a[2] = { wnh[5], wnh[7] };
            dot2p<2>(sb0, sb1, c2a, h2a, 32, o);
            red[tid]       = o[0];
            red[512 + tid] = o[1];
        }
        __syncthreads();
        if (upd) {
            COMB(0, v6);
            float s6a = s5a + sigm(v6.x) * (sigm(v6.z) - s5a);
            float s6b = s5b + sigm(v6.y) * (sigm(v6.w) - s5b);
            COMB(1, v8);
            float s8a = s5a + sigm(v8.x) * (fmaxf(v8.z, 0.f) - s5a);
            float s8b = s5b + sigm(v8.y) * (fmaxf(v8.w, 0.f) - s5b);
            suma += s6a + s8a;
            sumb += s6b + s8b;
            float hn0 = suma * 0.125f;
            float hn1 = sumb * 0.125f;
            out[(size_t)t * SZ + e0] = hn0;
            out[(size_t)t * SZ + e1] = hn1;
            g_h[e0] = hn0;
            g_h[e1] = hn1;
            hp0 = hn0; hp1 = hn1;
            if (t == TT - 1) {                     // hiddens[-1][None] tail
                out[(size_t)TT * SZ + e0] = hn0;
                out[(size_t)TT * SZ + e1] = hn1;
            }
        }
        grid_bar();   // h_new visible before next step's LVL0
    }
}

extern "C" void kernel_launch(void* const* d_in, const int* in_sizes, int n_in,
                              void* d_out, int out_size) {
    const float* x  = (const float*)d_in[0];   // (T, B, H) f32
    const float* W0 = (const float*)d_in[1];   // (2H, 2H) f32
    const float* Ws = (const float*)d_in[2];   // (8, H, 2H) f32
    float* out = (float*)d_out;

    cudaFuncSetAttribute(darts_kernel,
                         cudaFuncAttributeMaxDynamicSharedMemorySize, SMEM_BYTES);
    darts_kernel<<<NCTA, NTHR, SMEM_BYTES>>>(x, W0, Ws, out);
}

// round 11
// speedup vs baseline: 1.5464x; 1.0328x over previous
#include <cuda_runtime.h>
#include <math.h>

// Problem constants
#define TT   1024
#define BB   64
#define HH   512
#define H2   1024
#define SZ   (BB * HH)        // 32768 floats per state
#define NCTA 128
#define NTHR 512

// SMEM: w0 8 cols x 1024 k (32KB) + 8 nodes x 8 cols x 512 k (128KB)
#define SM_W0 (8 * 1024)
#define SMEM_FLOATS (SM_W0 + 8 * 8 * 512)
#define SMEM_BYTES  (SMEM_FLOATS * 4)     // 163840

typedef unsigned long long ull;

// Device-global scratch. State slots: 0:s0 1:s1 2:s2 3:s3 4:s5
__device__ __align__(16) float g_state[5 * SZ];
__device__ __align__(16) float g_h[SZ];
__device__ ull g_bar = 0ULL;              // monotonic counter: graph-replay-safe

__device__ __forceinline__ void grid_bar() {
    __syncthreads();
    if (threadIdx.x == 0) {
        __threadfence();    // publish + CCTL.IVALL invalidate of this SM's L1D
        ull my = atomicAdd(&g_bar, 1ULL);
        ull target = (my / (ull)NCTA + 1ULL) * (ull)NCTA;
        while (*((volatile ull*)&g_bar) < target) __nanosleep(64);
        __threadfence();
    }
    __syncthreads();
}

__device__ __forceinline__ float sigm(float x) { return 1.0f / (1.0f + expf(-x)); }

// Packed f32x2 FMA (sm_103a FFMA2)
__device__ __forceinline__ void fma2(ull& d, ull a, ull b) {
    asm("fma.rn.f32x2 %0, %1, %2, %0;" : "+l"(d) : "l"(a), "l"(b));
}

// Reduce a packed accumulator: intra-pair sum + 8-way butterfly over ksl lanes.
__device__ __forceinline__ float redu(ull a) {
    float lo, hi;
    asm("mov.b64 {%0,%1}, %2;" : "=f"(lo), "=f"(hi) : "l"(a));
    float v = lo + hi;
    v += __shfl_xor_sync(0xffffffffu, v, 1);
    v += __shfl_xor_sync(0xffffffffu, v, 2);
    v += __shfl_xor_sync(0xffffffffu, v, 4);
    return v;
}

// K=512 dot: one state row (this thread's k-slice: 16 floats strided j*32+koff)
// against 8 weight columns for each of NN nodes. acc[n][c] packed f32x2.
template <int NN>
__device__ __forceinline__ void dot512(const float* __restrict__ srow,
                                       const float* const* wb,
                                       int koff, ull (*acc)[8]) {
#pragma unroll 4
    for (int j = 0; j < 16; j++) {
        ulonglong2 s = *(const ulonglong2*)(srow + j * 32 + koff);
#pragma unroll
        for (int n = 0; n < NN; n++) {
#pragma unroll
            for (int c = 0; c < 8; c++) {
                ulonglong2 w = *(const ulonglong2*)(wb[n] + c * 512 + j * 32 + koff);
                fma2(acc[n][c], s.x, w.x);
                fma2(acc[n][c], s.y, w.y);
            }
        }
    }
}

// Half of the K=1024 W0 dot (16 j-chunks), weight column stride 1024.
__device__ __forceinline__ void dotW0(const float* __restrict__ srow,
                                      const float* __restrict__ w0,
                                      int wofs, int koff, ull* acc) {
#pragma unroll 4
    for (int j = 0; j < 16; j++) {
        ulonglong2 s = *(const ulonglong2*)(srow + j * 32 + koff);
#pragma unroll
        for (int c = 0; c < 8; c++) {
            ulonglong2 w = *(const ulonglong2*)(w0 + c * 1024 + wofs + j * 32 + koff);
            fma2(acc[c], s.x, w.x);
            fma2(acc[c], s.y, w.y);
        }
    }
}

__global__ void __launch_bounds__(NTHR, 1)
darts_kernel(const float* __restrict__ x,
             const float* __restrict__ W0,
             const float* __restrict__ Ws,
             float* __restrict__ out) {
    extern __shared__ float sm[];
    float* w0s = sm;            // [8 oc][1024 k]
    float* wns = sm + SM_W0;    // [8 node][8 oc][512 k]

    const int tid = threadIdx.x;
    const int Jb  = blockIdx.x * 4;

    // ---- Stage weight column slices (once; reused 1024 steps) ----
    // oc = jj*2 + part: part0 = c-col (J), part1 = h-col (J+512)
    for (int p = tid; p < 8 * 1024; p += NTHR) {
        int k = p >> 3, oc = p & 7;
        int J = Jb + (oc >> 1) + (oc & 1) * HH;
        w0s[oc * 1024 + k] = W0[(size_t)k * H2 + J];
    }
    for (int p = tid; p < 8 * 8 * 512; p += NTHR) {
        int node = p >> 12, rr = p & 4095;
        int k = rr >> 3, oc = rr & 7;
        int J = Jb + (oc >> 1) + (oc & 1) * HH;
        wns[(node * 8 + oc) * 512 + k] =
            Ws[(size_t)node * HH * H2 + (size_t)k * H2 + J];
    }

    // ---- Thread mapping: warp owns 4 rows; lane = ksl + 8*r ----
    const int warp = tid >> 5;
    const int lane = tid & 31;
    const int ksl  = lane & 7;
    const int r    = lane >> 3;
    const int row  = warp * 4 + r;
    const int koff = ksl * 4;                 // float offset within 128-float j-chunk
    const bool upd = (ksl == 0);              // updater lane for this row

    const float* hrow = g_h + row * HH;
    float* gs0 = g_state + 0 * SZ + row * HH;
    float* gs1 = g_state + 1 * SZ + row * HH;
    float* gs2 = g_state + 2 * SZ + row * HH;
    float* gs3 = g_state + 3 * SZ + row * HH;
    float* gs5 = g_state + 4 * SZ + row * HH;

    const float* wn[8];
#pragma unroll
    for (int i = 0; i < 8; i++) wn[i] = wns + i * 8 * 512;

    // Updater-held per-(row, jj) state
    float hp[4] = {0.f, 0.f, 0.f, 0.f};
    float s0[4], s1[4], s2[4], s3[4], s5[4], sum[4];

    // h0 = zeros (each CTA owns its 4 columns for all rows)
    if (upd) *(float4*)(g_h + row * HH + Jb) = make_float4(0.f, 0.f, 0.f, 0.f);
    grid_bar();

    for (int t = 0; t < TT; t++) {
        // ===== LVL0: s0 = highway(x, h_prev) with W0 (K=1024) =====
        {
            ull a[8];
#pragma unroll
            for (int c = 0; c < 8; c++) a[c] = 0ULL;
            const float* xr = x + (size_t)t * SZ + row * HH;
            dotW0(xr,   w0s, 0,   koff, a);
            dotW0(hrow, w0s, 512, koff, a);
            float v[8];
#pragma unroll
            for (int c = 0; c < 8; c++) v[c] = redu(a[c]);
            if (upd) {
#pragma unroll
                for (int jj = 0; jj < 4; jj++) {
                    float cg = sigm(v[2 * jj]);
                    float hg = tanhf(v[2 * jj + 1]);
                    s0[jj] = hp[jj] + cg * (hg - hp[jj]);
                }
                *(float4*)(gs0 - row * HH + row * HH + Jb) =
                    make_float4(s0[0], s0[1], s0[2], s0[3]);
            }
        }
        grid_bar();

        // ===== LVL1: node0 (pred s0, sigmoid) -> s1 =====
        {
            ull a[1][8];
#pragma unroll
            for (int c = 0; c < 8; c++) a[0][c] = 0ULL;
            const float* wb[1] = { wn[0] };
            dot512<1>(gs0, wb, koff, a);
            float v[8];
#pragma unroll
            for (int c = 0; c < 8; c++) v[c] = redu(a[0][c]);
            if (upd) {
#pragma unroll
                for (int jj = 0; jj < 4; jj++) {
                    s1[jj] = s0[jj] + sigm(v[2 * jj]) * (sigm(v[2 * jj + 1]) - s0[jj]);
                    sum[jj] = s1[jj];
                }
                *(float4*)(gs1 + Jb) = make_float4(s1[0], s1[1], s1[2], s1[3]);
            }
        }
        grid_bar();

        // ===== LVL2: nodes 1,2 (relu) then node 3 (identity), all pred s1 =====
        {
            ull a[2][8];
#pragma unroll
            for (int n = 0; n < 2; n++)
#pragma unroll
                for (int c = 0; c < 8; c++) a[n][c] = 0ULL;
            const float* wb2[2] = { wn[1], wn[2] };
            dot512<2>(gs1, wb2, koff, a);
            float v12[16];
#pragma unroll
            for (int n = 0; n < 2; n++)
#pragma unroll
                for (int c = 0; c < 8; c++) v12[n * 8 + c] = redu(a[n][c]);

            ull a3[1][8];
#pragma unroll
            for (int c = 0; c < 8; c++) a3[0][c] = 0ULL;
            const float* wb3[1] = { wn[3] };
            dot512<1>(gs1, wb3, koff, a3);
            float v3[8];
#pragma unroll
            for (int c = 0; c < 8; c++) v3[c] = redu(a3[0][c]);

            if (upd) {
#pragma unroll
                for (int jj = 0; jj < 4; jj++) {
                    s2[jj] = s1[jj] + sigm(v12[2 * jj]) * (fmaxf(v12[2 * jj + 1], 0.f) - s1[jj]);
                    s3[jj] = s1[jj] + sigm(v12[8 + 2 * jj]) * (fmaxf(v12[8 + 2 * jj + 1], 0.f) - s1[jj]);
                    float s4 = s1[jj] + sigm(v3[2 * jj]) * (v3[2 * jj + 1] - s1[jj]);
                    sum[jj] += s2[jj] + s3[jj] + s4;
                }
                *(float4*)(gs2 + Jb) = make_float4(s2[0], s2[1], s2[2], s2[3]);
                *(float4*)(gs3 + Jb) = make_float4(s3[0], s3[1], s3[2], s3[3]);
            }
        }
        grid_bar();

        // ===== LVL3: node4 (pred s2, tanh) -> s5 ; node6 (pred s3, tanh) -> s7 =====
        {
            ull a4[1][8], a6[1][8];
#pragma unroll
            for (int c = 0; c < 8; c++) { a4[0][c] = 0ULL; a6[0][c] = 0ULL; }
            const float* wb4[1] = { wn[4] };
            dot512<1>(gs2, wb4, koff, a4);
            const float* wb6[1] = { wn[6] };
            dot512<1>(gs3, wb6, koff, a6);
            float v4[8], v6[8];
#pragma unroll
            for (int c = 0; c < 8; c++) { v4[c] = redu(a4[0][c]); v6[c] = redu(a6[0][c]); }
            if (upd) {
#pragma unroll
                for (int jj = 0; jj < 4; jj++) {
                    s5[jj] = s2[jj] + sigm(v4[2 * jj]) * (tanhf(v4[2 * jj + 1]) - s2[jj]);
                    float s7 = s3[jj] + sigm(v6[2 * jj]) * (tanhf(v6[2 * jj + 1]) - s3[jj]);
                    sum[jj] += s5[jj] + s7;
                }
                *(float4*)(gs5 + Jb) = make_float4(s5[0], s5[1], s5[2], s5[3]);
            }
        }
        grid_bar();

        // ===== LVL4: node5 (pred s5, sigmoid) ; node7 (pred s5, relu) =====
        {
            ull a[2][8];
#pragma unroll
            for (int n = 0; n < 2; n++)
#pragma unroll
                for (int c = 0; c < 8; c++) a[n][c] = 0ULL;
            const float* wb[2] = { wn[5], wn[7] };
            dot512<2>(gs5, wb, koff, a);
            float v[16];
#pragma unroll
            for (int n = 0; n < 2; n++)
#pragma unroll
                for (int c = 0; c < 8; c++) v[n * 8 + c] = redu(a[n][c]);
            if (upd) {
                float hn[4];
#pragma unroll
                for (int jj = 0; jj < 4; jj++) {
                    float s6 = s5[jj] + sigm(v[2 * jj]) * (sigm(v[2 * jj + 1]) - s5[jj]);
                    float s8 = s5[jj] + sigm(v[8 + 2 * jj]) * (fmaxf(v[8 + 2 * jj + 1], 0.f) - s5[jj]);
                    sum[jj] += s6 + s8;
                    hn[jj] = sum[jj] * 0.125f;
                    hp[jj] = hn[jj];
                }
                float4 hv = make_float4(hn[0], hn[1], hn[2], hn[3]);
                *(float4*)(out + (size_t)t * SZ + row * HH + Jb) = hv;
                *(float4*)(g_h + row * HH + Jb) = hv;
                if (t == TT - 1)
                    *(float4*)(out + (size_t)TT * SZ + row * HH + Jb) = hv;  // tail
            }
        }
        grid_bar();   // h_new visible before next step's LVL0
    }
}

extern "C" void kernel_launch(void* const* d_in, const int* in_sizes, int n_in,
                              void* d_out, int out_size) {
    const float* x  = (const float*)d_in[0];   // (T, B, H) f32
    const float* W0 = (const float*)d_in[1];   // (2H, 2H) f32
    const float* Ws = (const float*)d_in[2];   // (8, H, 2H) f32
    float* out = (float*)d_out;

    cudaFuncSetAttribute(darts_kernel,
                         cudaFuncAttributeMaxDynamicSharedMemorySize, SMEM_BYTES);
    darts_kernel<<<NCTA, NTHR, SMEM_BYTES>>>(x, W0, Ws, out);
}

// round 12
// speedup vs baseline: 1.7360x; 1.1226x over previous
#include <cuda_runtime.h>
#include <math.h>

// Problem constants
#define TT   1024
#define BB   64
#define HH   512
#define H2   1024
#define SZ   (BB * HH)        // 32768 floats per state
#define NCTA 128
#define NTHR 512

// SMEM: w0s [8 oc][1024 k], wns [64 f][512 k], pre [48 slots][64 rows]
#define SM_W0  (8 * 1024)
#define SM_WN  (64 * 512)
#define SM_PRE (SM_W0 + SM_WN)
#define SMEM_FLOATS (SM_PRE + 48 * 64)
#define SMEM_BYTES  (SMEM_FLOATS * 4)     // 176128 B

typedef unsigned long long ull;

// Device-global scratch. State slots: 0:s0 1:s1 2:s2 3:s3 4:s5
__device__ __align__(16) float g_state[5 * SZ];
__device__ __align__(16) float g_h[SZ];
__device__ ull g_bar = 0ULL;              // monotonic counter: graph-replay-safe

__device__ __forceinline__ void grid_bar() {
    __syncthreads();
    if (threadIdx.x == 0) {
        __threadfence();    // publish state + invalidate L1D so remote writes are seen
        ull my = atomicAdd(&g_bar, 1ULL);
        ull target = (my / (ull)NCTA + 1ULL) * (ull)NCTA;
        while (*((volatile ull*)&g_bar) < target) __nanosleep(64);
        __threadfence();
    }
    __syncthreads();
}

__device__ __forceinline__ float sigm(float x) { return 1.0f / (1.0f + expf(-x)); }

// Packed f32x2 FMA (sm_103a FFMA2)
__device__ __forceinline__ void fma2(ull& d, ull a, ull b) {
    asm("fma.rn.f32x2 %0, %1, %2, %0;" : "+l"(d) : "l"(a), "l"(b));
}

// One job: C[16 rows x 4 cols] over a K-chunk of 256 floats (8 j-iters).
// Thread handles rows {rowoff + 4q}, its 4-float K-slice per j (koff = ksl*4).
// Each j: 4 weight LDS.128 + 4 state LDG.128 -> 32 FMA2.
__device__ __forceinline__ void gemm_job(const float* __restrict__ src,
                                         const float* __restrict__ wsm,
                                         int wstride, int rowoff, int koff,
                                         ull acc[4][4]) {
#pragma unroll
    for (int j = 0; j < 8; j++) {
        const int base = j * 32 + koff;
        ulonglong2 w0 = *(const ulonglong2*)(wsm + 0 * wstride + base);
        ulonglong2 w1 = *(const ulonglong2*)(wsm + 1 * wstride + base);
        ulonglong2 w2 = *(const ulonglong2*)(wsm + 2 * wstride + base);
        ulonglong2 w3 = *(const ulonglong2*)(wsm + 3 * wstride + base);
#pragma unroll
        for (int q = 0; q < 4; q++) {
            ulonglong2 s = *(const ulonglong2*)(src + (rowoff + 4 * q) * HH + base);
            fma2(acc[q][0], s.x, w0.x); fma2(acc[q][0], s.y, w0.y);
            fma2(acc[q][1], s.x, w1.x); fma2(acc[q][1], s.y, w1.y);
            fma2(acc[q][2], s.x, w2.x); fma2(acc[q][2], s.y, w2.y);
            fma2(acc[q][3], s.x, w3.x); fma2(acc[q][3], s.y, w3.y);
        }
    }
}

// Reduce each packed acc across the 8 ksl lanes (full butterfly) and store
// scalars into the preact buffer from the ksl==0 lanes.
__device__ __forceinline__ void reduce_store(ull acc[4][4], float* __restrict__ pre,
                                             int slot0, int rowoff, bool store) {
#pragma unroll
    for (int q = 0; q < 4; q++)
#pragma unroll
        for (int c = 0; c < 4; c++) {
            float lo, hi;
            asm("mov.b64 {%0,%1}, %2;" : "=f"(lo), "=f"(hi) : "l"(acc[q][c]));
            float v = lo + hi;
            v += __shfl_xor_sync(0xffffffffu, v, 1);
            v += __shfl_xor_sync(0xffffffffu, v, 2);
            v += __shfl_xor_sync(0xffffffffu, v, 4);
            if (store) pre[(slot0 + c) * 64 + rowoff + 4 * q] = v;
        }
}

#define ZACC(acc) {                                                         \
    _Pragma("unroll") for (int q = 0; q < 4; q++)                           \
    _Pragma("unroll") for (int c = 0; c < 4; c++) acc[q][c] = 0ULL; }

__global__ void __launch_bounds__(NTHR, 1)
darts_kernel(const float* __restrict__ x,
             const float* __restrict__ W0,
             const float* __restrict__ Ws,
             float* __restrict__ out) {
    extern __shared__ float sm[];
    float* w0s = sm;              // [8 oc][1024]
    float* wns = sm + SM_W0;      // [64 f][512]  f = node*8 + oc
    float* pre = sm + SM_PRE;     // [48][64]

    const int tid = threadIdx.x;
    const int Jb  = blockIdx.x * 4;

    // ---- Stage weight column slices (once; reused 1024 steps) ----
    // oc = jj*2 + part: part0 = c-col (J), part1 = h-col (J+512)
    for (int p = tid; p < 8 * 1024; p += NTHR) {
        int k = p >> 3, oc = p & 7;
        int J = Jb + (oc >> 1) + (oc & 1) * HH;
        w0s[oc * 1024 + k] = W0[(size_t)k * H2 + J];
    }
    for (int p = tid; p < 64 * 512; p += NTHR) {
        int node = p >> 12, rr = p & 4095;
        int k = rr >> 3, oc = rr & 7;
        int J = Jb + (oc >> 1) + (oc & 1) * HH;
        wns[(node * 8 + oc) * 512 + k] =
            Ws[(size_t)node * HH * H2 + (size_t)k * H2 + J];
    }

    // ---- GEMM thread mapping: warp = 8 ksl x 4 rq; wg = warp>>2, ww = warp&3 ----
    const int warp = tid >> 5;
    const int lane = tid & 31;
    const int ksl  = lane & 7;
    const int rq   = lane >> 3;
    const int wg   = warp >> 2;
    const int ww   = warp & 3;
    const int rowoff = ww * 16 + rq;      // thread rows: rowoff + 4q
    const int koff   = ksl * 4;
    const bool st    = (ksl == 0);

    // ---- Updater mapping: tid<256 owns one (row, jj) element ----
    const bool upd = (tid < 256);
    const int urow = tid >> 2;
    const int jj   = tid & 3;
    const int jj2  = jj * 2;
    const int eidx = urow * HH + Jb + jj;

    if (upd) g_h[eidx] = 0.f;             // h0 = zeros (all CTAs cover all of g_h)

    float hp = 0.f, s0 = 0.f, s1 = 0.f, s2 = 0.f, s3 = 0.f, s5 = 0.f, sum = 0.f;

    grid_bar();   // weights staged + g_h zeros visible

    for (int t = 0; t < TT; t++) {
        // ===== LVL0: s0 = highway([x|h] @ W0), K=1024 as 4 quarters x 2 oc-quads =====
#pragma unroll
        for (int s = 0; s < 2; s++) {
            int job = wg * 2 + s;             // 0..7
            int oq  = job & 1;                // oc quad
            int kq  = job >> 1;               // K quarter
            const float* src = (kq < 2) ? (x + (size_t)t * SZ + kq * 256)
                                        : (g_h + (kq - 2) * 256);
            ull acc[4][4]; ZACC(acc);
            gemm_job(src, w0s + oq * 4 * 1024 + kq * 256, 1024, rowoff, koff, acc);
            reduce_store(acc, pre, kq * 8 + oq * 4, rowoff, st);
        }
        __syncthreads();
        if (upd) {
            float cc = pre[(0 + jj2) * 64 + urow] + pre[(8 + jj2) * 64 + urow]
                     + pre[(16 + jj2) * 64 + urow] + pre[(24 + jj2) * 64 + urow];
            float hh = pre[(1 + jj2) * 64 + urow] + pre[(9 + jj2) * 64 + urow]
                     + pre[(17 + jj2) * 64 + urow] + pre[(25 + jj2) * 64 + urow];
            s0 = hp + sigm(cc) * (tanhf(hh) - hp);
            g_state[0 * SZ + eidx] = s0;
        }
        grid_bar();

        // ===== LVL1: node0 (pred s0, sigmoid). 4 jobs: (oq, kh) = (wg&1, wg>>1) =====
        {
            int oq = wg & 1, kh = wg >> 1;
            ull acc[4][4]; ZACC(acc);
            gemm_job(g_state + 0 * SZ + kh * 256,
                     wns + (0 + oq * 4) * 512 + kh * 256, 512, rowoff, koff, acc);
            reduce_store(acc, pre, kh * 8 + oq * 4, rowoff, st);
        }
        __syncthreads();
        if (upd) {
            float cc = pre[(jj2) * 64 + urow] + pre[(8 + jj2) * 64 + urow];
            float hh = pre[(1 + jj2) * 64 + urow] + pre[(9 + jj2) * 64 + urow];
            s1 = s0 + sigm(cc) * (sigm(hh) - s0);
            g_state[1 * SZ + eidx] = s1;
            sum = s1;
        }
        grid_bar();

        // ===== LVL2: nodes 1,2,3 (pred s1). 12 jobs: fq 0..5 x kh, 3 per wg =====
#pragma unroll
        for (int s = 0; s < 3; s++) {
            int job = wg * 3 + s;             // 0..11
            int fq  = job >> 1;               // col quad within level (0..5)
            int kh  = job & 1;
            ull acc[4][4]; ZACC(acc);
            gemm_job(g_state + 1 * SZ + kh * 256,
                     wns + (8 + fq * 4) * 512 + kh * 256, 512, rowoff, koff, acc);
            reduce_store(acc, pre, kh * 24 + fq * 4, rowoff, st);
        }
        __syncthreads();
        if (upd) {
            float cc, hh;
            cc = pre[(jj2) * 64 + urow] + pre[(24 + jj2) * 64 + urow];
            hh = pre[(1 + jj2) * 64 + urow] + pre[(25 + jj2) * 64 + urow];
            s2 = s1 + sigm(cc) * (fmaxf(hh, 0.f) - s1);
            cc = pre[(8 + jj2) * 64 + urow] + pre[(32 + jj2) * 64 + urow];
            hh = pre[(9 + jj2) * 64 + urow] + pre[(33 + jj2) * 64 + urow];
            s3 = s1 + sigm(cc) * (fmaxf(hh, 0.f) - s1);
            cc = pre[(16 + jj2) * 64 + urow] + pre[(40 + jj2) * 64 + urow];
            hh = pre[(17 + jj2) * 64 + urow] + pre[(41 + jj2) * 64 + urow];
            float s4 = s1 + sigm(cc) * (hh - s1);
            g_state[2 * SZ + eidx] = s2;
            g_state[3 * SZ + eidx] = s3;
            sum += s2 + s3 + s4;
        }
        grid_bar();

        // ===== LVL3: node4 (pred s2, tanh), node6 (pred s3, tanh). 8 jobs, 2/wg =====
#pragma unroll
        for (int s = 0; s < 2; s++) {
            int job = wg * 2 + s;             // 0..7
            int fq  = job >> 1;               // 0..3 (0,1 -> node4; 2,3 -> node6)
            int kh  = job & 1;
            const float* src = g_state + ((fq < 2) ? 2 : 3) * SZ + kh * 256;
            int f = (fq < 2) ? (32 + fq * 4) : (48 + (fq - 2) * 4);
            ull acc[4][4]; ZACC(acc);
            gemm_job(src, wns + f * 512 + kh * 256, 512, rowoff, koff, acc);
            reduce_store(acc, pre, kh * 16 + fq * 4, rowoff, st);
        }
        __syncthreads();
        if (upd) {
            float cc, hh;
            cc = pre[(jj2) * 64 + urow] + pre[(16 + jj2) * 64 + urow];
            hh = pre[(1 + jj2) * 64 + urow] + pre[(17 + jj2) * 64 + urow];
            s5 = s2 + sigm(cc) * (tanhf(hh) - s2);
            cc = pre[(8 + jj2) * 64 + urow] + pre[(24 + jj2) * 64 + urow];
            hh = pre[(9 + jj2) * 64 + urow] + pre[(25 + jj2) * 64 + urow];
            float s7 = s3 + sigm(cc) * (tanhf(hh) - s3);
            g_state[4 * SZ + eidx] = s5;
            sum += s5 + s7;
        }
        grid_bar();

        // ===== LVL4: node5 (sigmoid), node7 (relu), both pred s5. 8 jobs, 2/wg =====
#pragma unroll
        for (int s = 0; s < 2; s++) {
            int job = wg * 2 + s;
            int fq  = job >> 1;               // 0,1 -> node5; 2,3 -> node7
            int kh  = job & 1;
            int f = (fq < 2) ? (40 + fq * 4) : (56 + (fq - 2) * 4);
            ull acc[4][4]; ZACC(acc);
            gemm_job(g_state + 4 * SZ + kh * 256,
                     wns + f * 512 + kh * 256, 512, rowoff, koff, acc);
            reduce_store(acc, pre, kh * 16 + fq * 4, rowoff, st);
        }
        __syncthreads();
        if (upd) {
            float cc, hh;
            cc = pre[(jj2) * 64 + urow] + pre[(16 + jj2) * 64 + urow];
            hh = pre[(1 + jj2) * 64 + urow] + pre[(17 + jj2) * 64 + urow];
            float s6 = s5 + sigm(cc) * (sigm(hh) - s5);
            cc = pre[(8 + jj2) * 64 + urow] + pre[(24 + jj2) * 64 + urow];
            hh = pre[(9 + jj2) * 64 + urow] + pre[(25 + jj2) * 64 + urow];
            float s8 = s5 + sigm(cc) * (fmaxf(hh, 0.f) - s5);
            sum += s6 + s8;
            float hn = sum * 0.125f;
            out[(size_t)t * SZ + eidx] = hn;
            g_h[eidx] = hn;
            hp = hn;
            if (t == TT - 1) out[(size_t)TT * SZ + eidx] = hn;   // hiddens[-1][None]
        }
        grid_bar();   // h_new visible before next step's LVL0
    }
}

extern "C" void kernel_launch(void* const* d_in, const int* in_sizes, int n_in,
                              void* d_out, int out_size) {
    const float* x  = (const float*)d_in[0];   // (T, B, H) f32
    const float* W0 = (const float*)d_in[1];   // (2H, 2H) f32
    const float* Ws = (const float*)d_in[2];   // (8, H, 2H) f32
    float* out = (float*)d_out;

    cudaFuncSetAttribute(darts_kernel,
                         cudaFuncAttributeMaxDynamicSharedMemorySize, SMEM_BYTES);
    darts_kernel<<<NCTA, NTHR, SMEM_BYTES>>>(x, W0, Ws, out);
}

// round 13
// speedup vs baseline: 1.7372x; 1.0007x over previous
#include <cuda_runtime.h>
#include <math.h>

// Problem constants
#define TT   1024
#define BB   64
#define HH   512
#define H2   1024
#define SZ   (BB * HH)        // 32768 floats per state
#define NCTA 128
#define NTHR 512

// SMEM: w0s [8 oc][1024 k], wns [64 f][512 k], pre [48 slots][64 rows]
#define SM_W0  (8 * 1024)
#define SM_WN  (64 * 512)
#define SM_PRE (SM_W0 + SM_WN)
#define SMEM_FLOATS (SM_PRE + 48 * 64)
#define SMEM_BYTES  (SMEM_FLOATS * 4)     // 176128 B

typedef unsigned long long ull;

// Device-global scratch. State slots: 0:s0 1:s1 2:s2 3:s3 4:s5
__device__ __align__(16) float g_state[5 * SZ];
__device__ __align__(16) float g_h[SZ];
__device__ ull g_bar = 0ULL;              // monotonic counter: graph-replay-safe

__device__ __forceinline__ void grid_bar() {
    __syncthreads();
    if (threadIdx.x == 0) {
        __threadfence();    // publish state + invalidate L1D so remote writes are seen
        ull my = atomicAdd(&g_bar, 1ULL);
        ull target = (my / (ull)NCTA + 1ULL) * (ull)NCTA;
        while (*((volatile ull*)&g_bar) < target) __nanosleep(64);
        __threadfence();
    }
    __syncthreads();
}

__device__ __forceinline__ float sigm(float x) { return 1.0f / (1.0f + expf(-x)); }

// Packed f32x2 FMA (sm_103a FFMA2)
__device__ __forceinline__ void fma2(ull& d, ull a, ull b) {
    asm("fma.rn.f32x2 %0, %1, %2, %0;" : "+l"(d) : "l"(a), "l"(b));
}

// One job: C[16 rows x 4 cols] over a K-chunk of 256 floats (8 j-iters).
// Thread handles rows {rowoff + 4q}, its 4-float K-slice per j (koff = ksl*4).
// Each j: 4 weight LDS.128 + 4 state LDG.128 -> 32 FMA2.
__device__ __forceinline__ void gemm_job(const float* __restrict__ src,
                                         const float* __restrict__ wsm,
                                         int wstride, int rowoff, int koff,
                                         ull acc[4][4]) {
#pragma unroll
    for (int j = 0; j < 8; j++) {
        const int base = j * 32 + koff;
        ulonglong2 w0 = *(const ulonglong2*)(wsm + 0 * wstride + base);
        ulonglong2 w1 = *(const ulonglong2*)(wsm + 1 * wstride + base);
        ulonglong2 w2 = *(const ulonglong2*)(wsm + 2 * wstride + base);
        ulonglong2 w3 = *(const ulonglong2*)(wsm + 3 * wstride + base);
#pragma unroll
        for (int q = 0; q < 4; q++) {
            ulonglong2 s = *(const ulonglong2*)(src + (rowoff + 4 * q) * HH + base);
            fma2(acc[q][0], s.x, w0.x); fma2(acc[q][0], s.y, w0.y);
            fma2(acc[q][1], s.x, w1.x); fma2(acc[q][1], s.y, w1.y);
            fma2(acc[q][2], s.x, w2.x); fma2(acc[q][2], s.y, w2.y);
            fma2(acc[q][3], s.x, w3.x); fma2(acc[q][3], s.y, w3.y);
        }
    }
}

// Reduce each packed acc across the 8 ksl lanes (full butterfly) and store
// scalars into the preact buffer from the ksl==0 lanes.
__device__ __forceinline__ void reduce_store(ull acc[4][4], float* __restrict__ pre,
                                             int slot0, int rowoff, bool store) {
#pragma unroll
    for (int q = 0; q < 4; q++)
#pragma unroll
        for (int c = 0; c < 4; c++) {
            float lo, hi;
            asm("mov.b64 {%0,%1}, %2;" : "=f"(lo), "=f"(hi) : "l"(acc[q][c]));
            float v = lo + hi;
            v += __shfl_xor_sync(0xffffffffu, v, 1);
            v += __shfl_xor_sync(0xffffffffu, v, 2);
            v += __shfl_xor_sync(0xffffffffu, v, 4);
            if (store) pre[(slot0 + c) * 64 + rowoff + 4 * q] = v;
        }
}

#define ZACC(acc) {                                                         \
    _Pragma("unroll") for (int q = 0; q < 4; q++)                           \
    _Pragma("unroll") for (int c = 0; c < 4; c++) acc[q][c] = 0ULL; }

__global__ void __launch_bounds__(NTHR, 1)
darts_kernel(const float* __restrict__ x,
             const float* __restrict__ W0,
             const float* __restrict__ Ws,
             float* __restrict__ out) {
    extern __shared__ float sm[];
    float* w0s = sm;              // [8 oc][1024]
    float* wns = sm + SM_W0;      // [64 f][512]  f = node*8 + oc
    float* pre = sm + SM_PRE;     // [48][64]

    const int tid = threadIdx.x;
    const int Jb  = blockIdx.x * 4;

    // ---- Stage weight column slices (once; reused 1024 steps) ----
    // oc = jj*2 + part: part0 = c-col (J), part1 = h-col (J+512)
    for (int p = tid; p < 8 * 1024; p += NTHR) {
        int k = p >> 3, oc = p & 7;
        int J = Jb + (oc >> 1) + (oc & 1) * HH;
        w0s[oc * 1024 + k] = W0[(size_t)k * H2 + J];
    }
    for (int p = tid; p < 64 * 512; p += NTHR) {
        int node = p >> 12, rr = p & 4095;
        int k = rr >> 3, oc = rr & 7;
        int J = Jb + (oc >> 1) + (oc & 1) * HH;
        wns[(node * 8 + oc) * 512 + k] =
            Ws[(size_t)node * HH * H2 + (size_t)k * H2 + J];
    }

    // ---- GEMM thread mapping: warp = 8 ksl x 4 rq; wg = warp>>2, ww = warp&3 ----
    const int warp = tid >> 5;
    const int lane = tid & 31;
    const int ksl  = lane & 7;
    const int rq   = lane >> 3;
    const int wg   = warp >> 2;
    const int ww   = warp & 3;
    const int rowoff = ww * 16 + rq;      // thread rows: rowoff + 4q
    const int koff   = ksl * 4;
    const bool st    = (ksl == 0);

    // ---- Updater mapping: tid<256 owns one (row, jj) element ----
    const bool upd = (tid < 256);
    const int urow = tid >> 2;
    const int jj   = tid & 3;
    const int jj2  = jj * 2;
    const int eidx = urow * HH + Jb + jj;

    if (upd) g_h[eidx] = 0.f;             // h0 = zeros (all CTAs cover all of g_h)

    float hp = 0.f, s0 = 0.f, s1 = 0.f, s2 = 0.f, s3 = 0.f, s5 = 0.f, sum = 0.f;

    grid_bar();   // weights staged + g_h zeros visible

    for (int t = 0; t < TT; t++) {
        // ===== LVL0: s0 = highway([x|h] @ W0), K=1024 as 4 quarters x 2 oc-quads =====
#pragma unroll
        for (int s = 0; s < 2; s++) {
            int job = wg * 2 + s;             // 0..7
            int oq  = job & 1;                // oc quad
            int kq  = job >> 1;               // K quarter
            const float* src = (kq < 2) ? (x + (size_t)t * SZ + kq * 256)
                                        : (g_h + (kq - 2) * 256);
            ull acc[4][4]; ZACC(acc);
            gemm_job(src, w0s + oq * 4 * 1024 + kq * 256, 1024, rowoff, koff, acc);
            reduce_store(acc, pre, kq * 8 + oq * 4, rowoff, st);
        }
        __syncthreads();
        if (upd) {
            float cc = pre[(0 + jj2) * 64 + urow] + pre[(8 + jj2) * 64 + urow]
                     + pre[(16 + jj2) * 64 + urow] + pre[(24 + jj2) * 64 + urow];
            float hh = pre[(1 + jj2) * 64 + urow] + pre[(9 + jj2) * 64 + urow]
                     + pre[(17 + jj2) * 64 + urow] + pre[(25 + jj2) * 64 + urow];
            s0 = hp + sigm(cc) * (tanhf(hh) - hp);
            g_state[0 * SZ + eidx] = s0;
        }
        grid_bar();

        // ===== LVL1: node0 (pred s0, sigmoid). 4 jobs: (oq, kh) = (wg&1, wg>>1) =====
        {
            int oq = wg & 1, kh = wg >> 1;
            ull acc[4][4]; ZACC(acc);
            gemm_job(g_state + 0 * SZ + kh * 256,
                     wns + (0 + oq * 4) * 512 + kh * 256, 512, rowoff, koff, acc);
            reduce_store(acc, pre, kh * 8 + oq * 4, rowoff, st);
        }
        __syncthreads();
        if (upd) {
            float cc = pre[(jj2) * 64 + urow] + pre[(8 + jj2) * 64 + urow];
            float hh = pre[(1 + jj2) * 64 + urow] + pre[(9 + jj2) * 64 + urow];
            s1 = s0 + sigm(cc) * (sigm(hh) - s0);
            g_state[1 * SZ + eidx] = s1;
            sum = s1;
        }
        grid_bar();

        // ===== LVL2: nodes 1,2,3 (pred s1). 12 jobs: fq 0..5 x kh, 3 per wg =====
#pragma unroll
        for (int s = 0; s < 3; s++) {
            int job = wg * 3 + s;             // 0..11
            int fq  = job >> 1;               // col quad within level (0..5)
            int kh  = job & 1;
            ull acc[4][4]; ZACC(acc);
            gemm_job(g_state + 1 * SZ + kh * 256,
                     wns + (8 + fq * 4) * 512 + kh * 256, 512, rowoff, koff, acc);
            reduce_store(acc, pre, kh * 24 + fq * 4, rowoff, st);
        }
        __syncthreads();
        if (upd) {
            float cc, hh;
            cc = pre[(jj2) * 64 + urow] + pre[(24 + jj2) * 64 + urow];
            hh = pre[(1 + jj2) * 64 + urow] + pre[(25 + jj2) * 64 + urow];
            s2 = s1 + sigm(cc) * (fmaxf(hh, 0.f) - s1);
            cc = pre[(8 + jj2) * 64 + urow] + pre[(32 + jj2) * 64 + urow];
            hh = pre[(9 + jj2) * 64 + urow] + pre[(33 + jj2) * 64 + urow];
            s3 = s1 + sigm(cc) * (fmaxf(hh, 0.f) - s1);
            cc = pre[(16 + jj2) * 64 + urow] + pre[(40 + jj2) * 64 + urow];
            hh = pre[(17 + jj2) * 64 + urow] + pre[(41 + jj2) * 64 + urow];
            float s4 = s1 + sigm(cc) * (hh - s1);
            g_state[2 * SZ + eidx] = s2;
            g_state[3 * SZ + eidx] = s3;
            sum += s2 + s3 + s4;
        }
        grid_bar();

        // ===== LVL3: node4 (pred s2, tanh), node6 (pred s3, tanh). 8 jobs, 2/wg =====
#pragma unroll
        for (int s = 0; s < 2; s++) {
            int job = wg * 2 + s;             // 0..7
            int fq  = job >> 1;               // 0..3 (0,1 -> node4; 2,3 -> node6)
            int kh  = job & 1;
            const float* src = g_state + ((fq < 2) ? 2 : 3) * SZ + kh * 256;
            int f = (fq < 2) ? (32 + fq * 4) : (48 + (fq - 2) * 4);
            ull acc[4][4]; ZACC(acc);
            gemm_job(src, wns + f * 512 + kh * 256, 512, rowoff, koff, acc);
            reduce_store(acc, pre, kh * 16 + fq * 4, rowoff, st);
        }
        __syncthreads();
        if (upd) {
            float cc, hh;
            cc = pre[(jj2) * 64 + urow] + pre[(16 + jj2) * 64 + urow];
            hh = pre[(1 + jj2) * 64 + urow] + pre[(17 + jj2) * 64 + urow];
            s5 = s2 + sigm(cc) * (tanhf(hh) - s2);
            cc = pre[(8 + jj2) * 64 + urow] + pre[(24 + jj2) * 64 + urow];
            hh = pre[(9 + jj2) * 64 + urow] + pre[(25 + jj2) * 64 + urow];
            float s7 = s3 + sigm(cc) * (tanhf(hh) - s3);
            g_state[4 * SZ + eidx] = s5;
            sum += s5 + s7;
        }
        grid_bar();

        // ===== LVL4: node5 (sigmoid), node7 (relu), both pred s5. 8 jobs, 2/wg =====
#pragma unroll
        for (int s = 0; s < 2; s++) {
            int job = wg * 2 + s;
            int fq  = job >> 1;               // 0,1 -> node5; 2,3 -> node7
            int kh  = job & 1;
            int f = (fq < 2) ? (40 + fq * 4) : (56 + (fq - 2) * 4);
            ull acc[4][4]; ZACC(acc);
            gemm_job(g_state + 4 * SZ + kh * 256,
                     wns + f * 512 + kh * 256, 512, rowoff, koff, acc);
            reduce_store(acc, pre, kh * 16 + fq * 4, rowoff, st);
        }
        __syncthreads();
        if (upd) {
            float cc, hh;
            cc = pre[(jj2) * 64 + urow] + pre[(16 + jj2) * 64 + urow];
            hh = pre[(1 + jj2) * 64 + urow] + pre[(17 + jj2) * 64 + urow];
            float s6 = s5 + sigm(cc) * (sigm(hh) - s5);
            cc = pre[(8 + jj2) * 64 + urow] + pre[(24 + jj2) * 64 + urow];
            hh = pre[(9 + jj2) * 64 + urow] + pre[(25 + jj2) * 64 + urow];
            float s8 = s5 + sigm(cc) * (fmaxf(hh, 0.f) - s5);
            sum += s6 + s8;
            float hn = sum * 0.125f;
            out[(size_t)t * SZ + eidx] = hn;
            g_h[eidx] = hn;
            hp = hn;
            if (t == TT - 1) out[(size_t)TT * SZ + eidx] = hn;   // hiddens[-1][None]
        }
        grid_bar();   // h_new visible before next step's LVL0
    }
}

extern "C" void kernel_launch(void* const* d_in, const int* in_sizes, int n_in,
                              void* d_out, int out_size) {
    const float* x  = (const float*)d_in[0];   // (T, B, H) f32
    const float* W0 = (const float*)d_in[1];   // (2H, 2H) f32
    const float* Ws = (const float*)d_in[2];   // (8, H, 2H) f32
    float* out = (float*)d_out;

    cudaFuncSetAttribute(darts_kernel,
                         cudaFuncAttributeMaxDynamicSharedMemorySize, SMEM_BYTES);
    darts_kernel<<<NCTA, NTHR, SMEM_BYTES>>>(x, W0, Ws, out);
}